// round 2
// baseline (speedup 1.0000x reference)
#include <cuda_runtime.h>
#include <cuda_bf16.h>
#include <math.h>

// ---------------- problem constants ----------------
#define BSZ   4
#define LSEQ  2048
#define DM    1024
#define DI    2048
#define NS    16
#define RK    64          // DT_RANK
#define E2    96          // DT_RANK + 2*D_STATE
#define TT    8
#define HH    16
#define WW    16
#define BT    32          // BSZ*TT frames
#define OUT_MAIN (BSZ*LSEQ*DM)   // 8388608

// ---------------- device scratch ----------------
__device__ float g_x    [(size_t)BSZ*DI*LSEQ];   // (b,d,l)
__device__ float g_z    [(size_t)BSZ*DI*LSEQ];   // (b,d,l)
__device__ float g_xc   [(size_t)BSZ*DI*LSEQ];   // conv+silu, (b,d,l)
__device__ float g_xcT  [(size_t)BSZ*LSEQ*DI];   // (b,l,d)
__device__ float g_delta[(size_t)BSZ*DI*LSEQ];   // (b,d,l)
__device__ float g_ygT  [(size_t)BSZ*LSEQ*DI];   // gated y, (b,l,d)
__device__ float g_xdbl [(size_t)BSZ*LSEQ*E2];   // (b,l,96)
__device__ float g_feat [BT*DI];
__device__ float g_A    [DI*NS];
__device__ float g_alphaF[DI];
__device__ float g_att  [DI];
__device__ float g_colmax[NS];
__device__ float g_colmin[NS];
__device__ float g_attmax[1];
// DFT tables + mask
__device__ float g_cw[9*16], g_sw[9*16];     // [kw][w]
__device__ float g_ch[16*16], g_sh[16*16];   // [kh][h]
__device__ float g_mask[16*9];               // [kh][kw]

// ---------------- K0: tables ----------------
__global__ void init_tables_kernel() {
    int tid = threadIdx.x;
    if (tid < 144) {
        int kw = tid / 16, w = tid % 16;
        float a = (float)(w * kw) / 8.0f;
        g_cw[kw*16+w] = cospif(a);
        g_sw[kw*16+w] = sinpif(a);
    }
    {
        int kh = tid / 16, h = tid % 16;
        float a = (float)(h * kh) / 8.0f;
        g_ch[kh*16+h] = cospif(a);
        g_sh[kh*16+h] = sinpif(a);
    }
    if (tid < 144) {
        int kh = tid / 9, kw = tid % 9;
        int i = (kh + 8) & 15;       // fftshift position along H
        int j = (kw + 4) % 9;        // fftshift position along Wr
        float hh = (i - 8) / 16.0f;
        float ww = (j - 4) / 9.0f;
        g_mask[tid] = (sqrtf(hh*hh + ww*ww) >= 0.5f) ? 1.0f : 0.0f;
    }
}

// ---------------- generic NT GEMM: C[m][n] = sum_k A[m][k]*B[n][k] ----------------
// mode 0: in_proj  -> g_x / g_z      (M=4096, B=hidden_states)
// mode 1: x_proj   -> g_xdbl         (M=96,   B=g_xcT)
// mode 2: dt_proj  -> softplus -> g_delta (M=2048, B=g_xdbl, K=64, ldb=96)
// mode 3: out_proj -> d_out          (M=1024, B=g_ygT)
#define BM 128
#define BN 128
#define BKK 16

__global__ __launch_bounds__(256)
void gemm_nt_kernel(const float* __restrict__ A, const float* __restrict__ Bext,
                    int M, int N, int K, int lda, int ldb,
                    int mode, const float* __restrict__ bias,
                    float* __restrict__ Cout)
{
    __shared__ float As[BKK][BM];
    __shared__ float Bs[BKK][BN];

    const float* Bp = Bext;
    if (mode == 1) Bp = g_xcT;
    else if (mode == 2) Bp = g_xdbl;
    else if (mode == 3) Bp = g_ygT;

    int bm = blockIdx.y * BM;
    int bn = blockIdx.x * BN;
    int tid = threadIdx.x;
    int tx = tid & 15, ty = tid >> 4;

    float acc[8][8];
#pragma unroll
    for (int i = 0; i < 8; i++)
#pragma unroll
        for (int j = 0; j < 8; j++) acc[i][j] = 0.0f;

    for (int k0 = 0; k0 < K; k0 += BKK) {
#pragma unroll
        for (int r = 0; r < 2; r++) {
            int q   = tid + r * 256;
            int row = q >> 2;
            int kq  = (q & 3) * 4;
            int ar  = bm + row; if (ar > M - 1) ar = M - 1;
            float4 av = *(const float4*)(A + (size_t)ar * lda + k0 + kq);
            As[kq+0][row] = av.x; As[kq+1][row] = av.y;
            As[kq+2][row] = av.z; As[kq+3][row] = av.w;
            float4 bv = *(const float4*)(Bp + (size_t)(bn + row) * ldb + k0 + kq);
            Bs[kq+0][row] = bv.x; Bs[kq+1][row] = bv.y;
            Bs[kq+2][row] = bv.z; Bs[kq+3][row] = bv.w;
        }
        __syncthreads();
#pragma unroll
        for (int kk = 0; kk < BKK; kk++) {
            float4 a0 = *(const float4*)&As[kk][ty*8];
            float4 a1 = *(const float4*)&As[kk][ty*8+4];
            float4 b0 = *(const float4*)&Bs[kk][tx*8];
            float4 b1 = *(const float4*)&Bs[kk][tx*8+4];
            float aa[8] = {a0.x,a0.y,a0.z,a0.w,a1.x,a1.y,a1.z,a1.w};
            float bb[8] = {b0.x,b0.y,b0.z,b0.w,b1.x,b1.y,b1.z,b1.w};
#pragma unroll
            for (int i = 0; i < 8; i++)
#pragma unroll
                for (int j = 0; j < 8; j++)
                    acc[i][j] += aa[i] * bb[j];
        }
        __syncthreads();
    }

#pragma unroll
    for (int i = 0; i < 8; i++) {
        int m = bm + ty*8 + i;
        if (m >= M) continue;
#pragma unroll
        for (int j = 0; j < 8; j++) {
            int n = bn + tx*8 + j;
            float v = acc[i][j];
            if (mode == 0) {
                int b_ = n >> 11, l_ = n & 2047;
                if (m < DI) g_x[((size_t)(b_*DI + m))*LSEQ + l_] = v;
                else        g_z[((size_t)(b_*DI + (m - DI)))*LSEQ + l_] = v;
            } else if (mode == 1) {
                g_xdbl[(size_t)n * E2 + m] = v;
            } else if (mode == 2) {
                float sp = v + bias[m];
                sp = (sp > 20.0f) ? sp : log1pf(__expf(sp));
                int b_ = n >> 11, l_ = n & 2047;
                g_delta[((size_t)(b_*DI + m))*LSEQ + l_] = sp;
            } else {
                Cout[(size_t)n * DM + m] = v;
            }
        }
    }
}

// ---------------- K2: per-(frame,channel) rfft2 band features ----------------
__global__ __launch_bounds__(256)
void fft_feat_kernel() {
    __shared__ float xp[256];
    __shared__ float Yr[144], Yi[144];
    __shared__ float sA[256], sH[256];
    int bid = blockIdx.x;              // f*2048 + c
    int f = bid >> 11, c = bid & 2047;
    int b = f >> 3,  t = f & 7;
    int tid = threadIdx.x;

    xp[tid] = g_x[((size_t)(b*DI + c))*LSEQ + t*256 + tid];
    __syncthreads();

    if (tid < 144) {                   // row DFT: Y[h][kw]
        int h = tid / 9, kw = tid % 9;
        float yr = 0.f, yi = 0.f;
#pragma unroll
        for (int w = 0; w < 16; w++) {
            float v = xp[h*16 + w];
            yr += v * g_cw[kw*16 + w];
            yi -= v * g_sw[kw*16 + w];
        }
        Yr[tid] = yr; Yi[tid] = yi;
    }
    __syncthreads();

    float a = 0.f, hi = 0.f;
    if (tid < 144) {                   // column DFT + magnitude
        int kh = tid / 9, kw = tid % 9;
        float zr = 0.f, zi = 0.f;
#pragma unroll
        for (int h = 0; h < 16; h++) {
            float cc = g_ch[kh*16 + h], ss = g_sh[kh*16 + h];
            float yr = Yr[h*9 + kw], yi = Yi[h*9 + kw];
            zr += yr*cc + yi*ss;
            zi += yi*cc - yr*ss;
        }
        float mag = sqrtf(zr*zr + zi*zi + 1e-8f);
        a = mag; hi = mag * g_mask[tid];
    }
    sA[tid] = a; sH[tid] = hi;
    __syncthreads();
    for (int off = 128; off > 0; off >>= 1) {
        if (tid < off) { sA[tid] += sA[tid+off]; sH[tid] += sH[tid+off]; }
        __syncthreads();
    }
    if (tid == 0) g_feat[f*DI + c] = sH[0] / (sA[0] + 1e-8f);
}

// ---------------- K3: align_loss + channel softmax ----------------
__global__ __launch_bounds__(1024)
void loss_alpha_kernel(float* __restrict__ loss_out) {
    __shared__ float rn[32];
    __shared__ float sFM[DI];
    __shared__ float red[32];
    int tid = threadIdx.x;
    int wid = tid >> 5, lane = tid & 31;

    // per-frame inverse norms (warp w handles frame w)
    {
        float acc = 0.f;
        for (int c = lane; c < DI; c += 32) { float v = g_feat[wid*DI + c]; acc += v*v; }
        for (int o = 16; o; o >>= 1) acc += __shfl_xor_sync(0xffffffffu, acc, o);
        if (lane == 0) rn[wid] = 1.0f / fmaxf(sqrtf(acc), 1e-12f);
    }
    __syncthreads();

    // g[c] = sum_f fn, gg = ||g||^2 ; fmean[c]
    float gg = 0.f;
    for (int c = tid; c < DI; c += 1024) {
        float gv = 0.f, fm = 0.f;
        for (int f = 0; f < 32; f++) {
            float v = g_feat[f*DI + c];
            gv += v * rn[f];
            fm += v;
        }
        gg += gv * gv;
        sFM[c] = fm * (1.0f / 32.0f);
    }
    for (int o = 16; o; o >>= 1) gg += __shfl_xor_sync(0xffffffffu, gg, o);
    if (lane == 0) red[wid] = gg;
    __syncthreads();
    if (tid == 0) {
        float s = 0.f;
        for (int i = 0; i < 32; i++) s += red[i];
        loss_out[0] = 1.0f - s * (1.0f / (BT*BT));
    }
    __syncthreads();

    // softmax over sFM -> g_alphaF
    float mx = -1e30f;
    for (int c = tid; c < DI; c += 1024) mx = fmaxf(mx, sFM[c]);
    for (int o = 16; o; o >>= 1) mx = fmaxf(mx, __shfl_xor_sync(0xffffffffu, mx, o));
    if (lane == 0) red[wid] = mx;
    __syncthreads();
    if (tid == 0) {
        float m = red[0];
        for (int i = 1; i < 32; i++) m = fmaxf(m, red[i]);
        red[0] = m;
    }
    __syncthreads();
    mx = red[0];
    __syncthreads();
    float se = 0.f;
    for (int c = tid; c < DI; c += 1024) { float e = __expf(sFM[c] - mx); sFM[c] = e; se += e; }
    for (int o = 16; o; o >>= 1) se += __shfl_xor_sync(0xffffffffu, se, o);
    if (lane == 0) red[wid] = se;
    __syncthreads();
    if (tid == 0) {
        float s = 0.f;
        for (int i = 0; i < 32; i++) s += red[i];
        red[0] = s;
    }
    __syncthreads();
    float inv = 1.0f / red[0];
    for (int c = tid; c < DI; c += 1024) g_alphaF[c] = sFM[c] * inv;
}

// ---------------- K3b1: attention norms, col max/min of A_log ----------------
__global__ __launch_bounds__(256)
void att_kernel(const float* __restrict__ A_log) {
    __shared__ float red[256];
    int tid = threadIdx.x;
    if (tid < NS) {
        float mx = -1e30f, mn = 1e30f;
        for (int d = 0; d < DI; d++) {
            float v = A_log[d*NS + tid];
            mx = fmaxf(mx, v); mn = fminf(mn, v);
        }
        g_colmax[tid] = mx; g_colmin[tid] = mn;
    }
    float am = 0.f;
    for (int d = tid; d < DI; d += 256) {
        float s = 0.f;
#pragma unroll
        for (int n = 0; n < NS; n++) { float e = expf(A_log[d*NS + n]); s += e*e; }
        float att = sqrtf(s);
        g_att[d] = att;
        am = fmaxf(am, att);
    }
    red[tid] = am;
    __syncthreads();
    for (int o = 128; o; o >>= 1) {
        if (tid < o) red[tid] = fmaxf(red[tid], red[tid+o]);
        __syncthreads();
    }
    if (tid == 0) g_attmax[0] = red[0];
}

// ---------------- K3b2: build A = -exp(blended A_log) ----------------
__global__ void build_A_kernel(const float* __restrict__ A_log) {
    int d = blockIdx.x * blockDim.x + threadIdx.x;
    if (d >= DI) return;
    float alpha = g_alphaF[d] * (1.0f - g_att[d] / (g_attmax[0] + 1e-8f));
    alpha = fminf(fmaxf(alpha, 0.0f), 1.0f);
#pragma unroll
    for (int n = 0; n < NS; n++) {
        float al = A_log[d*NS + n];
        float an = (1.0f - alpha) * al + alpha * (g_colmax[n] + g_colmin[n] - al);
        g_A[d*NS + n] = -expf(an);
    }
}

// ---------------- K4: depthwise causal conv(4) + SiLU ----------------
__global__ __launch_bounds__(256)
void conv_silu_kernel(const float* __restrict__ cw, const float* __restrict__ cb) {
    int idx = blockIdx.x * blockDim.x + threadIdx.x;
    if (idx >= BSZ*DI*LSEQ) return;
    int l = idx & 2047;
    int d = (idx >> 11) & 2047;
    float acc = cb[d];
    const float* xr = g_x + (size_t)(idx - l);
#pragma unroll
    for (int j = 0; j < 4; j++) {
        int li = l - 3 + j;
        if (li >= 0) acc += xr[li] * cw[d*4 + j];
    }
    float sg = 1.0f / (1.0f + __expf(-acc));
    g_xc[idx] = acc * sg;
}

// ---------------- K4b: transpose (b,d,l) -> (b,l,d) ----------------
__global__ void transpose_kernel() {
    __shared__ float tile[32][33];
    int b  = blockIdx.z;
    int l0 = blockIdx.x * 32, d0 = blockIdx.y * 32;
    int tx = threadIdx.x, ty = threadIdx.y;
    const float* src = g_xc  + (size_t)b * DI * LSEQ;
    float*       dst = g_xcT + (size_t)b * LSEQ * DI;
#pragma unroll
    for (int j = 0; j < 32; j += 8)
        tile[ty+j][tx] = src[(size_t)(d0 + ty + j) * LSEQ + l0 + tx];
    __syncthreads();
#pragma unroll
    for (int j = 0; j < 32; j += 8)
        dst[(size_t)(l0 + ty + j) * DI + d0 + tx] = tile[tx][ty+j];
}

// ---------------- K6: selective scan (warp = 2 channels x 16 states) ----------------
__global__ __launch_bounds__(256)
void scan_kernel(const float* __restrict__ Dp) {
    int tid  = blockIdx.x * blockDim.x + threadIdx.x;
    int warp = tid >> 5;
    int lane = tid & 31;
    int b = warp >> 10;
    int d = ((warp & 1023) << 1) + (lane >> 4);
    int n = lane & 15;

    const float An = g_A[d*NS + n];
    const float Dd = Dp[d];
    const float* dl_p = g_delta + ((size_t)(b*DI + d)) * LSEQ;
    const float* u_p  = g_xc    + ((size_t)(b*DI + d)) * LSEQ;
    const float* z_p  = g_z     + ((size_t)(b*DI + d)) * LSEQ;
    const float* bc_p = g_xdbl  + (size_t)b * LSEQ * E2;
    float* yo = g_ygT + (size_t)b * LSEQ * DI + d;

    float s = 0.0f;
    for (int t = 0; t < LSEQ; t++) {
        float dl = dl_p[t];
        float u  = u_p[t];
        float Bv = bc_p[t*E2 + RK + n];
        float Cv = bc_p[t*E2 + RK + NS + n];
        s = s * __expf(dl * An) + (dl * u) * Bv;
        float p = s * Cv;
        p += __shfl_xor_sync(0xffffffffu, p, 8);
        p += __shfl_xor_sync(0xffffffffu, p, 4);
        p += __shfl_xor_sync(0xffffffffu, p, 2);
        p += __shfl_xor_sync(0xffffffffu, p, 1);
        if (n == 0) {
            float y = p + u * Dd;
            float z = z_p[t];
            float sg = 1.0f / (1.0f + __expf(-z));
            yo[(size_t)t * DI] = y * (z * sg);
        }
    }
}

// ---------------- launch ----------------
extern "C" void kernel_launch(void* const* d_in, const int* in_sizes, int n_in,
                              void* d_out, int out_size) {
    const float* hs  = (const float*)d_in[0];
    const float* ipw = (const float*)d_in[4];
    const float* cw  = (const float*)d_in[5];
    const float* cb  = (const float*)d_in[6];
    const float* xpw = (const float*)d_in[7];
    const float* dtw = (const float*)d_in[8];
    const float* dtb = (const float*)d_in[9];
    const float* alog= (const float*)d_in[10];
    const float* Dp  = (const float*)d_in[11];
    const float* opw = (const float*)d_in[12];
    float* out = (float*)d_out;

    init_tables_kernel<<<1, 256>>>();

    // GEMM1: xz = in_proj_w @ hs^T  -> g_x, g_z
    gemm_nt_kernel<<<dim3(64, 32), 256>>>(ipw, hs, 2*DI, BSZ*LSEQ, DM, DM, DM,
                                          0, nullptr, nullptr);

    // channel alignment features + loss + softmax, A blend
    fft_feat_kernel<<<BT*DI, 256>>>();
    loss_alpha_kernel<<<1, 1024>>>(out + OUT_MAIN);
    att_kernel<<<1, 256>>>(alog);
    build_A_kernel<<<DI/256, 256>>>(alog);

    // conv + silu, transpose
    conv_silu_kernel<<<(BSZ*DI*LSEQ)/256, 256>>>(cw, cb);
    transpose_kernel<<<dim3(LSEQ/32, DI/32, BSZ), dim3(32, 8)>>>();

    // GEMM2: x_dbl = x_proj_w @ xcT^T
    gemm_nt_kernel<<<dim3(64, 1), 256>>>(xpw, nullptr, E2, BSZ*LSEQ, DI, DI, DI,
                                         1, nullptr, nullptr);

    // GEMM3: delta = softplus(dt_proj_w @ dt_low^T + b)
    gemm_nt_kernel<<<dim3(64, 16), 256>>>(dtw, nullptr, DI, BSZ*LSEQ, RK, RK, E2,
                                          2, dtb, nullptr);

    // selective scan + gating -> g_ygT
    scan_kernel<<<(BSZ*DI*NS)/256, 256>>>(Dp);

    // GEMM4: out = out_proj_w @ yg^T -> d_out
    gemm_nt_kernel<<<dim3(64, 8), 256>>>(opw, nullptr, DM, BSZ*LSEQ, DI, DI, DI,
                                         3, nullptr, out);
}

// round 4
// speedup vs baseline: 1.5965x; 1.5965x over previous
#include <cuda_runtime.h>
#include <cuda_bf16.h>
#include <math.h>
#include <stdint.h>

#define BSZ 4
#define LSEQ 2048
#define DM 1024
#define DI 2048
#define NS 16
#define RK 64
#define E2 96
#define OUT_MAIN (BSZ*LSEQ*DM)

__device__ float g_x[(size_t)BSZ*DI*LSEQ];
__device__ float g_z[(size_t)BSZ*DI*LSEQ];
__device__ float g_xc[(size_t)BSZ*DI*LSEQ];
__device__ float g_xcT[(size_t)BSZ*LSEQ*DI];
__device__ float g_delta[(size_t)BSZ*DI*LSEQ];
__device__ float g_ygT[(size_t)BSZ*LSEQ*DI];
__device__ float g_xdbl[(size_t)BSZ*LSEQ*E2];
__device__ float g_feat[32*DI];
__device__ float g_A[DI*NS];
__device__ float g_alphaF[DI];
__device__ float g_att[DI];
__device__ float g_colmax[NS], g_colmin[NS], g_attmax[1];
__device__ float g_cw[9*16], g_sw[9*16], g_ch[16*16], g_sh[16*16], g_mask[16*9];

__device__ __forceinline__ uint32_t smem_u32(const void* p) {
    uint32_t a;
    asm("{ .reg .u64 t; cvta.to.shared.u64 t, %1; cvt.u32.u64 %0, t; }" : "=r"(a) : "l"(p));
    return a;
}
#define LDM4(r, addr) \
    asm volatile("ldmatrix.sync.aligned.m8n8.x4.shared.b16 {%0,%1,%2,%3}, [%4];" \
        : "=r"((r)[0]), "=r"((r)[1]), "=r"((r)[2]), "=r"((r)[3]) : "r"(addr))
#define MMA(c, a, b0v, b1v) \
    asm volatile("mma.sync.aligned.m16n8k16.row.col.f32.bf16.bf16.f32 " \
        "{%0,%1,%2,%3}, {%4,%5,%6,%7}, {%8,%9}, {%0,%1,%2,%3};" \
        : "+f"((c)[0]), "+f"((c)[1]), "+f"((c)[2]), "+f"((c)[3]) \
        : "r"((a)[0]), "r"((a)[1]), "r"((a)[2]), "r"((a)[3]), "r"(b0v), "r"(b1v))

// ---- K0: tables ----
__global__ void init_tables_kernel() {
    int tid = threadIdx.x;
    if (tid < 144) {
        int kw = tid/16, w = tid%16;
        float a = (float)(w*kw)/8.0f;
        g_cw[kw*16+w] = cospif(a); g_sw[kw*16+w] = sinpif(a);
    }
    { int kh = tid/16, h = tid%16;
      float a = (float)(h*kh)/8.0f;
      g_ch[kh*16+h] = cospif(a); g_sh[kh*16+h] = sinpif(a); }
    if (tid < 144) {
        int kh = tid/9, kw = tid%9;
        int i = (kh+8)&15, j = (kw+4)%9;
        float hh = (i-8)/16.0f, ww = (j-4)/9.0f;
        g_mask[tid] = (sqrtf(hh*hh+ww*ww) >= 0.5f) ? 1.0f : 0.0f;
    }
}

// ---- bf16x2-split tensor-core GEMM: D[m][n] = sum_k W[m][k]*X[n][k] ----
// row pitch in smem: 32 bf16 data padded to 40 (80 bytes) -> conflict-free ldmatrix
#define RP 80
#define T_AH 0
#define T_AL 10240
#define T_BH 20480
#define T_BL 30720

template<int MODE>
__global__ __launch_bounds__(256)
void gemm_mma_kernel(const float* __restrict__ W, int ldw, int wmax,
                     const float* __restrict__ Xext, int ldx, int K,
                     const float* __restrict__ bias, float* __restrict__ Out)
{
    __shared__ __align__(16) char sm[40960];
    const float* X = Xext;
    if (MODE==1) X = g_xcT; else if (MODE==2) X = g_xdbl; else if (MODE==3) X = g_ygT;

    int tid = threadIdx.x, wid = tid>>5, lane = tid&31;
    int wm = wid & 1, wn = wid >> 1;
    int i0 = blockIdx.y*128, j0 = blockIdx.x*128;
    uint32_t sb = smem_u32(sm);

    // fragment smem addresses (per lane)
    int frow = ((lane>>3)&1)*8 + (lane&7);
    uint32_t khalf = (uint32_t)(lane>>4)*16;
    uint32_t aAddr = sb + (uint32_t)(wm*64 + frow)*RP + khalf;       // +T_AH/T_AL, +mi*16*RP, +kk*2
    uint32_t bAddr = sb + (uint32_t)(wn*32 + frow)*RP + khalf;

    float acc[4][4][4];
#pragma unroll
    for (int a=0;a<4;a++)
#pragma unroll
        for (int b=0;b<4;b++)
#pragma unroll
            for (int q=0;q<4;q++) acc[a][b][q]=0.f;

    float4 stA[4], stB[4];
    int NC = K/32;

    auto gload = [&](int c) {
#pragma unroll
        for (int it=0; it<4; it++) {
            int idx = tid + it*256;
            int r = idx>>3, u = idx&7;
            int wr = i0 + r; if (wr > wmax) wr = wmax;
            stA[it] = *(const float4*)(W + (size_t)wr*ldw + c*32 + u*4);
            stB[it] = *(const float4*)(X + (size_t)(j0+r)*ldx + c*32 + u*4);
        }
    };
    auto sstore = [&]() {
#pragma unroll
        for (int it=0; it<4; it++) {
            int idx = tid + it*256;
            int r = idx>>3, u = idx&7;
            uint32_t off = (uint32_t)r*RP + (uint32_t)u*8;
            float4 v = stA[it];
            __nv_bfloat162 h01 = __floats2bfloat162_rn(v.x, v.y);
            __nv_bfloat162 h23 = __floats2bfloat162_rn(v.z, v.w);
            __nv_bfloat162 l01 = __floats2bfloat162_rn(v.x - __bfloat162float(h01.x),
                                                       v.y - __bfloat162float(h01.y));
            __nv_bfloat162 l23 = __floats2bfloat162_rn(v.z - __bfloat162float(h23.x),
                                                       v.w - __bfloat162float(h23.y));
            uint2 ph; ph.x = *(uint32_t*)&h01; ph.y = *(uint32_t*)&h23;
            uint2 pl; pl.x = *(uint32_t*)&l01; pl.y = *(uint32_t*)&l23;
            *(uint2*)(sm + T_AH + off) = ph;
            *(uint2*)(sm + T_AL + off) = pl;
            v = stB[it];
            h01 = __floats2bfloat162_rn(v.x, v.y);
            h23 = __floats2bfloat162_rn(v.z, v.w);
            l01 = __floats2bfloat162_rn(v.x - __bfloat162float(h01.x),
                                        v.y - __bfloat162float(h01.y));
            l23 = __floats2bfloat162_rn(v.z - __bfloat162float(h23.x),
                                        v.w - __bfloat162float(h23.y));
            ph.x = *(uint32_t*)&h01; ph.y = *(uint32_t*)&h23;
            pl.x = *(uint32_t*)&l01; pl.y = *(uint32_t*)&l23;
            *(uint2*)(sm + T_BH + off) = ph;
            *(uint2*)(sm + T_BL + off) = pl;
        }
    };

    gload(0); sstore();
    __syncthreads();

    for (int c = 0; c < NC; c++) {
        if (c+1 < NC) gload(c+1);
#pragma unroll
        for (int kk = 0; kk < 2; kk++) {
            uint32_t ko = (uint32_t)kk*32;
            uint32_t ah[4][4], al[4][4];
#pragma unroll
            for (int mi=0; mi<4; mi++) {
                LDM4(ah[mi], aAddr + T_AH + (uint32_t)mi*16*RP + ko);
                LDM4(al[mi], aAddr + T_AL + (uint32_t)mi*16*RP + ko);
            }
#pragma unroll
            for (int j=0; j<2; j++) {
                uint32_t bh[4], bl[4];
                LDM4(bh, bAddr + T_BH + (uint32_t)j*16*RP + ko);
                LDM4(bl, bAddr + T_BL + (uint32_t)j*16*RP + ko);
#pragma unroll
                for (int mi=0; mi<4; mi++) {
#pragma unroll
                    for (int nt=0; nt<2; nt++) {
                        float* cc = acc[mi][j*2+nt];
                        MMA(cc, ah[mi], bh[nt], bh[nt+2]);
                        MMA(cc, ah[mi], bl[nt], bl[nt+2]);
                        MMA(cc, al[mi], bh[nt], bh[nt+2]);
                    }
                }
            }
        }
        __syncthreads();
        if (c+1 < NC) {
            sstore();
            __syncthreads();
        }
    }

    // epilogue
#pragma unroll
    for (int mi=0; mi<4; mi++) {
        int mBase = i0 + wm*64 + mi*16 + (lane>>2);
#pragma unroll
        for (int ni=0; ni<4; ni++) {
            int n0 = j0 + wn*32 + ni*8 + (lane&3)*2;
            float* c = acc[mi][ni];
#pragma unroll
            for (int rr=0; rr<2; rr++) {
                int m = mBase + rr*8;
                float v0 = c[rr*2], v1 = c[rr*2+1];
                if (MODE==0) {
                    int b_ = n0>>11, l_ = n0&2047;
                    float* dst = (m < DI) ? (g_x + ((size_t)(b_*DI+m))*LSEQ + l_)
                                          : (g_z + ((size_t)(b_*DI+m-DI))*LSEQ + l_);
                    float2 o; o.x=v0; o.y=v1;
                    *(float2*)dst = o;
                } else if (MODE==1) {
                    if (m < E2) {
                        g_xdbl[(size_t)n0*E2 + m]     = v0;
                        g_xdbl[(size_t)(n0+1)*E2 + m] = v1;
                    }
                } else if (MODE==2) {
                    int b_ = n0>>11, l_ = n0&2047;
                    float bi = bias[m];
                    float s0 = v0 + bi, s1 = v1 + bi;
                    s0 = (s0 > 20.0f) ? s0 : log1pf(__expf(s0));
                    s1 = (s1 > 20.0f) ? s1 : log1pf(__expf(s1));
                    float2 o; o.x=s0; o.y=s1;
                    *(float2*)(g_delta + ((size_t)(b_*DI+m))*LSEQ + l_) = o;
                } else {
                    Out[(size_t)n0*DM + m]     = v0;
                    Out[(size_t)(n0+1)*DM + m] = v1;
                }
            }
        }
    }
}

// ---- K2: rfft2 band features ----
__global__ __launch_bounds__(256)
void fft_feat_kernel() {
    __shared__ float xp[256], Yr[144], Yi[144], sA[256], sH[256];
    int bid = blockIdx.x;
    int f = bid>>11, c = bid&2047;
    int b = f>>3, t = f&7;
    int tid = threadIdx.x;
    xp[tid] = g_x[((size_t)(b*DI+c))*LSEQ + t*256 + tid];
    __syncthreads();
    if (tid < 144) {
        int h = tid/9, kw = tid%9;
        float yr = 0.f, yi = 0.f;
#pragma unroll
        for (int w = 0; w < 16; w++) {
            float v = xp[h*16+w];
            yr += v*g_cw[kw*16+w]; yi -= v*g_sw[kw*16+w];
        }
        Yr[tid] = yr; Yi[tid] = yi;
    }
    __syncthreads();
    float a = 0.f, hi = 0.f;
    if (tid < 144) {
        int kh = tid/9, kw = tid%9;
        float zr = 0.f, zi = 0.f;
#pragma unroll
        for (int h = 0; h < 16; h++) {
            float cc = g_ch[kh*16+h], ss = g_sh[kh*16+h];
            float yr = Yr[h*9+kw], yi = Yi[h*9+kw];
            zr += yr*cc + yi*ss; zi += yi*cc - yr*ss;
        }
        float mag = sqrtf(zr*zr + zi*zi + 1e-8f);
        a = mag; hi = mag*g_mask[tid];
    }
    sA[tid] = a; sH[tid] = hi;
    __syncthreads();
    for (int off = 128; off > 0; off >>= 1) {
        if (tid < off) { sA[tid] += sA[tid+off]; sH[tid] += sH[tid+off]; }
        __syncthreads();
    }
    if (tid == 0) g_feat[f*DI+c] = sH[0]/(sA[0]+1e-8f);
}

// ---- K3: loss + softmax ----
__global__ __launch_bounds__(1024)
void loss_alpha_kernel(float* __restrict__ loss_out) {
    __shared__ float rn[32], sFM[DI], red[32];
    int tid = threadIdx.x, wid = tid>>5, lane = tid&31;
    {
        float acc = 0.f;
        for (int c = lane; c < DI; c += 32) { float v = g_feat[wid*DI+c]; acc += v*v; }
        for (int o = 16; o; o >>= 1) acc += __shfl_xor_sync(0xffffffffu, acc, o);
        if (lane == 0) rn[wid] = 1.0f/fmaxf(sqrtf(acc), 1e-12f);
    }
    __syncthreads();
    float gg = 0.f;
    for (int c = tid; c < DI; c += 1024) {
        float gv = 0.f, fm = 0.f;
        for (int f = 0; f < 32; f++) { float v = g_feat[f*DI+c]; gv += v*rn[f]; fm += v; }
        gg += gv*gv; sFM[c] = fm*(1.0f/32.0f);
    }
    for (int o = 16; o; o >>= 1) gg += __shfl_xor_sync(0xffffffffu, gg, o);
    if (lane == 0) red[wid] = gg;
    __syncthreads();
    if (tid == 0) {
        float s = 0.f;
        for (int i = 0; i < 32; i++) s += red[i];
        loss_out[0] = 1.0f - s*(1.0f/1024.0f);
    }
    __syncthreads();
    float mx = -1e30f;
    for (int c = tid; c < DI; c += 1024) mx = fmaxf(mx, sFM[c]);
    for (int o = 16; o; o >>= 1) mx = fmaxf(mx, __shfl_xor_sync(0xffffffffu, mx, o));
    if (lane == 0) red[wid] = mx;
    __syncthreads();
    if (tid == 0) {
        float m = red[0];
        for (int i = 1; i < 32; i++) m = fmaxf(m, red[i]);
        red[0] = m;
    }
    __syncthreads();
    mx = red[0];
    __syncthreads();
    float se = 0.f;
    for (int c = tid; c < DI; c += 1024) { float e = __expf(sFM[c]-mx); sFM[c] = e; se += e; }
    for (int o = 16; o; o >>= 1) se += __shfl_xor_sync(0xffffffffu, se, o);
    if (lane == 0) red[wid] = se;
    __syncthreads();
    if (tid == 0) {
        float s = 0.f;
        for (int i = 0; i < 32; i++) s += red[i];
        red[0] = s;
    }
    __syncthreads();
    float inv = 1.0f/red[0];
    for (int c = tid; c < DI; c += 1024) g_alphaF[c] = sFM[c]*inv;
}

// ---- K3b ----
__global__ __launch_bounds__(256)
void att_kernel(const float* __restrict__ A_log) {
    __shared__ float red[256];
    int tid = threadIdx.x;
    if (tid < NS) {
        float mx = -1e30f, mn = 1e30f;
        for (int d = 0; d < DI; d++) {
            float v = A_log[d*NS+tid];
            mx = fmaxf(mx, v); mn = fminf(mn, v);
        }
        g_colmax[tid] = mx; g_colmin[tid] = mn;
    }
    float am = 0.f;
    for (int d = tid; d < DI; d += 256) {
        float s = 0.f;
#pragma unroll
        for (int n = 0; n < NS; n++) { float e = expf(A_log[d*NS+n]); s += e*e; }
        float att = sqrtf(s);
        g_att[d] = att; am = fmaxf(am, att);
    }
    red[tid] = am;
    __syncthreads();
    for (int o = 128; o; o >>= 1) {
        if (tid < o) red[tid] = fmaxf(red[tid], red[tid+o]);
        __syncthreads();
    }
    if (tid == 0) g_attmax[0] = red[0];
}

__global__ void build_A_kernel(const float* __restrict__ A_log) {
    int d = blockIdx.x*blockDim.x + threadIdx.x;
    if (d >= DI) return;
    float alpha = g_alphaF[d]*(1.0f - g_att[d]/(g_attmax[0]+1e-8f));
    alpha = fminf(fmaxf(alpha, 0.0f), 1.0f);
#pragma unroll
    for (int n = 0; n < NS; n++) {
        float al = A_log[d*NS+n];
        float an = (1.0f-alpha)*al + alpha*(g_colmax[n]+g_colmin[n]-al);
        g_A[d*NS+n] = -expf(an);
    }
}

// ---- K4: conv + silu ----
__global__ __launch_bounds__(256)
void conv_silu_kernel(const float* __restrict__ cw, const float* __restrict__ cb) {
    int idx = blockIdx.x*blockDim.x + threadIdx.x;
    if (idx >= BSZ*DI*LSEQ) return;
    int l = idx&2047, d = (idx>>11)&2047;
    float acc = cb[d];
    const float* xr = g_x + (size_t)(idx-l);
#pragma unroll
    for (int j = 0; j < 4; j++) {
        int li = l-3+j;
        if (li >= 0) acc += xr[li]*cw[d*4+j];
    }
    float sg = 1.0f/(1.0f+__expf(-acc));
    g_xc[idx] = acc*sg;
}

// ---- K4b: transpose ----
__global__ void transpose_kernel() {
    __shared__ float tile[32][33];
    int b = blockIdx.z;
    int l0 = blockIdx.x*32, d0 = blockIdx.y*32;
    int tx = threadIdx.x, ty = threadIdx.y;
    const float* src = g_xc + (size_t)b*DI*LSEQ;
    float* dst = g_xcT + (size_t)b*LSEQ*DI;
#pragma unroll
    for (int j = 0; j < 32; j += 8)
        tile[ty+j][tx] = src[(size_t)(d0+ty+j)*LSEQ + l0+tx];
    __syncthreads();
#pragma unroll
    for (int j = 0; j < 32; j += 8)
        dst[(size_t)(l0+ty+j)*DI + d0+tx] = tile[tx][ty+j];
}

// ---- K6: scan ----
__global__ __launch_bounds__(256)
void scan_kernel(const float* __restrict__ Dp) {
    int tid = blockIdx.x*blockDim.x + threadIdx.x;
    int warp = tid>>5, lane = tid&31;
    int b = warp>>10;
    int d = ((warp&1023)<<1) + (lane>>4);
    int n = lane&15;
    const float An = g_A[d*NS+n];
    const float Dd = Dp[d];
    const float* dl_p = g_delta + ((size_t)(b*DI+d))*LSEQ;
    const float* u_p  = g_xc    + ((size_t)(b*DI+d))*LSEQ;
    const float* z_p  = g_z     + ((size_t)(b*DI+d))*LSEQ;
    const float* bc_p = g_xdbl  + (size_t)b*LSEQ*E2;
    float* yo = g_ygT + (size_t)b*LSEQ*DI + d;
    float s = 0.0f;
    for (int t = 0; t < LSEQ; t++) {
        float dl = dl_p[t];
        float u = u_p[t];
        float Bv = bc_p[t*E2+RK+n];
        float Cv = bc_p[t*E2+RK+NS+n];
        s = s*__expf(dl*An) + (dl*u)*Bv;
        float p = s*Cv;
        p += __shfl_xor_sync(0xffffffffu, p, 8);
        p += __shfl_xor_sync(0xffffffffu, p, 4);
        p += __shfl_xor_sync(0xffffffffu, p, 2);
        p += __shfl_xor_sync(0xffffffffu, p, 1);
        if (n == 0) {
            float y = p + u*Dd;
            float z = z_p[t];
            float sg = 1.0f/(1.0f+__expf(-z));
            yo[(size_t)t*DI] = y*(z*sg);
        }
    }
}

// ---- launch ----
extern "C" void kernel_launch(void* const* d_in, const int* in_sizes, int n_in,
                              void* d_out, int out_size) {
    const float* hs  = (const float*)d_in[0];
    const float* ipw = (const float*)d_in[4];
    const float* cw  = (const float*)d_in[5];
    const float* cb  = (const float*)d_in[6];
    const float* xpw = (const float*)d_in[7];
    const float* dtw = (const float*)d_in[8];
    const float* dtb = (const float*)d_in[9];
    const float* alog= (const float*)d_in[10];
    const float* Dp  = (const float*)d_in[11];
    const float* opw = (const float*)d_in[12];
    float* out = (float*)d_out;

    init_tables_kernel<<<1, 256>>>();

    // GEMM1: xz = in_proj_w @ hs^T
    gemm_mma_kernel<0><<<dim3(64, 32), 256>>>(ipw, DM, 2*DI-1, hs, DM, DM, nullptr, nullptr);

    fft_feat_kernel<<<32*DI, 256>>>();
    loss_alpha_kernel<<<1, 1024>>>(out + OUT_MAIN);
    att_kernel<<<1, 256>>>(alog);
    build_A_kernel<<<DI/256, 256>>>(alog);

    conv_silu_kernel<<<(BSZ*DI*LSEQ)/256, 256>>>(cw, cb);
    transpose_kernel<<<dim3(LSEQ/32, DI/32, BSZ), dim3(32, 8)>>>();

    // GEMM2: x_dbl = x_proj_w @ xcT^T
    gemm_mma_kernel<1><<<dim3(64, 1), 256>>>(xpw, DI, E2-1, nullptr, DI, DI, nullptr, nullptr);
    // GEMM3: delta = softplus(dt_proj_w @ dt_low^T + b)
    gemm_mma_kernel<2><<<dim3(64, 16), 256>>>(dtw, RK, DI-1, nullptr, E2, RK, dtb, nullptr);

    scan_kernel<<<(BSZ*DI*NS)/256, 256>>>(Dp);

    // GEMM4: out = out_proj_w @ yg^T
    gemm_mma_kernel<3><<<dim3(64, 8), 256>>>(opw, DI, DM-1, nullptr, DI, DI, nullptr, out);
}